// round 6
// baseline (speedup 1.0000x reference)
#include <cuda_runtime.h>
#include <math.h>
#include <stdint.h>

#define BB 4
#define LL 2048
#define DD 1024
#define DIN 1024
#define NS 8
#define RR 64
#define DBLW 80
#define SEG 16
#define SEGL 128
#define MTOT (BB*LL)
#define SPLITK 4

// ---------------- scratch ----------------
__device__ float g_xnorm[MTOT*DD];
__device__ float g_xz[MTOT*2*DIN];
__device__ float g_xconv[MTOT*DIN];
__device__ float g_dbl[MTOT*DBLW];
__device__ float g_dblp[SPLITK*MTOT*DBLW];
__device__ float g_dt[MTOT*DIN];
__device__ float g_y[MTOT*DIN];
__device__ float g_segA[BB*SEG*NS*DIN];
__device__ float g_segB[BB*SEG*NS*DIN];
__device__ float g_hin[BB*SEG*NS*DIN];
__device__ float g_w_in[2*DIN*DD];
__device__ float g_w_x[DBLW*DIN];
__device__ float g_w_dt[DIN*RR];
__device__ float g_w_out[DD*DIN];

// ---------------- helpers ----------------
__device__ __forceinline__ float rnd_tf32(float f) {
    uint32_t u;
    asm("cvt.rna.tf32.f32 %0, %1;" : "=r"(u) : "f"(f));
    return __uint_as_float(u);
}

__device__ __forceinline__ void mma_tf32(float c[4], const uint32_t a[4], const uint32_t b[2]) {
    asm volatile(
        "mma.sync.aligned.m16n8k8.row.col.f32.tf32.tf32.f32 "
        "{%0,%1,%2,%3}, {%4,%5,%6,%7}, {%8,%9}, {%0,%1,%2,%3};"
        : "+f"(c[0]), "+f"(c[1]), "+f"(c[2]), "+f"(c[3])
        : "r"(a[0]), "r"(a[1]), "r"(a[2]), "r"(a[3]), "r"(b[0]), "r"(b[1]));
}

__device__ __forceinline__ void cp16(uint32_t dst, const void* src, bool v) {
    int sz = v ? 16 : 0;
    asm volatile("cp.async.cg.shared.global [%0], [%1], 16, %2;\n"
                 :: "r"(dst), "l"(src), "r"(sz));
}

// ---------------- weight convert ----------------
#define NWI (2*DIN*DD)
#define NWX (DBLW*DIN)
#define NWDT (DIN*RR)
#define NWO (DD*DIN)
__global__ __launch_bounds__(256) void cvt_weights(const float4* __restrict__ iw,
                                                   const float4* __restrict__ xw,
                                                   const float4* __restrict__ dw,
                                                   const float4* __restrict__ ow) {
    int i = blockIdx.x * 256 + threadIdx.x;
    const float4* src;
    float4* dst;
    if (i < NWI/4) { src = iw + i; dst = (float4*)g_w_in + i; }
    else if ((i -= NWI/4) < NWX/4) { src = xw + i; dst = (float4*)g_w_x + i; }
    else if ((i -= NWX/4) < NWDT/4) { src = dw + i; dst = (float4*)g_w_dt + i; }
    else if ((i -= NWDT/4) < NWO/4) { src = ow + i; dst = (float4*)g_w_out + i; }
    else return;
    float4 v = *src;
    v.x = rnd_tf32(v.x); v.y = rnd_tf32(v.y);
    v.z = rnd_tf32(v.z); v.w = rnd_tf32(v.w);
    *dst = v;
}

// ---------------- RMSNorm ----------------
__global__ __launch_bounds__(256) void rmsnorm_kernel(const float* __restrict__ x,
                                                      const float* __restrict__ w) {
    const int row = blockIdx.x;
    const float4 v = *((const float4*)(x + (size_t)row * DD) + threadIdx.x);
    float ss = v.x*v.x + v.y*v.y + v.z*v.z + v.w*v.w;
#pragma unroll
    for (int o = 16; o > 0; o >>= 1) ss += __shfl_xor_sync(0xffffffffu, ss, o);
    __shared__ float red[8];
    if ((threadIdx.x & 31) == 0) red[threadIdx.x >> 5] = ss;
    __syncthreads();
    float tot = 0.f;
#pragma unroll
    for (int i = 0; i < 8; i++) tot += red[i];
    const float sc = rsqrtf(tot * (1.f / DD) + 1e-5f);
    const float4 wv = *((const float4*)w + threadIdx.x);
    float4 o;
    o.x = rnd_tf32(v.x * sc * wv.x);
    o.y = rnd_tf32(v.y * sc * wv.y);
    o.z = rnd_tf32(v.z * sc * wv.z);
    o.w = rnd_tf32(v.w * sc * wv.w);
    *((float4*)(g_xnorm + (size_t)row * DD) + threadIdx.x) = o;
}

// ---------------- TF32 tensor-core GEMM, BM=128 BN=256 BK=32, 3-stage ----------------
// 8 warps, warp grid 2(M) x 4(N), 64x64 per warp.
#define GSTAGES 3
#define GSTRIDE 36
#define ASTGF (128*GSTRIDE)
#define BSTGF (256*GSTRIDE)
#define ASTGB (ASTGF*4)
#define BSTGB (BSTGF*4)
#define GSMEM (GSTAGES*(ASTGB+BSTGB))   // 165888 bytes

__global__ __launch_bounds__(256, 1) void gemm_tf32(
    const float* __restrict__ A, int lda,
    const float* __restrict__ W, int ldw,
    float* __restrict__ C, int ldc, size_t cstride,
    int K, int E,
    const float* __restrict__ bias, int epi)
{
    extern __shared__ float smem[];
    float* sA = smem;
    float* sB = smem + GSTAGES * ASTGF;

    const int tid = threadIdx.x;
    const int lane = tid & 31;
    const int wid = tid >> 5;
    const int m0 = blockIdx.y * 128;
    const int e0 = blockIdx.x * 256;
    const int z = blockIdx.z;
    const int wm = (wid & 1) * 64;
    const int wn = (wid >> 1) * 64;

    const int prow = tid >> 3;        // 0..31
    const int pk = (tid & 7) * 4;     // 0..28

    const uint32_t sAu = (uint32_t)__cvta_generic_to_shared(sA);
    const uint32_t sBu = (uint32_t)__cvta_generic_to_shared(sB);

    const float* aP[4];
    uint32_t dAo[4];
#pragma unroll
    for (int c = 0; c < 4; c++) {
        const int r = prow + 32 * c;
        aP[c] = A + (size_t)(m0 + r) * lda + (size_t)z * K + pk;
        dAo[c] = sAu + (r * GSTRIDE + pk) * 4;
    }
    const float* wP[8];
    bool wv[8];
    uint32_t dBo[8];
#pragma unroll
    for (int c = 0; c < 8; c++) {
        const int r = prow + 32 * c;
        const int er = e0 + r;
        wv[c] = er < E;
        wP[c] = W + (size_t)(wv[c] ? er : 0) * ldw + (size_t)z * K + pk;
        dBo[c] = sBu + (r * GSTRIDE + pk) * 4;
    }

    float acc[4][8][4];
#pragma unroll
    for (int i = 0; i < 4; i++)
#pragma unroll
        for (int j = 0; j < 8; j++)
#pragma unroll
            for (int l = 0; l < 4; l++) acc[i][j][l] = 0.f;

    const int T = K / 32;

#pragma unroll
    for (int p = 0; p < GSTAGES - 1; p++) {
        const int ko = p * 32;
#pragma unroll
        for (int c = 0; c < 4; c++) cp16(dAo[c] + p * ASTGB, aP[c] + ko, true);
#pragma unroll
        for (int c = 0; c < 8; c++) cp16(dBo[c] + p * BSTGB, wP[c] + ko, wv[c]);
        asm volatile("cp.async.commit_group;\n");
    }

    const int g = lane >> 2;
    const int tg = lane & 3;

    for (int t = 0; t < T; t++) {
        asm volatile("cp.async.wait_group 1;\n");
        __syncthreads();

        const int stg = t % GSTAGES;
        const float* At = sA + stg * ASTGF;
        const float* Bt = sB + stg * BSTGF;

#pragma unroll
        for (int ks = 0; ks < 4; ks++) {
            const int kk = ks * 8;
            uint32_t af[4][4];
            uint32_t bf[8][2];
#pragma unroll
            for (int mt = 0; mt < 4; mt++) {
                const int mb = wm + mt * 16 + g;
                af[mt][0] = __float_as_uint(At[mb * GSTRIDE + kk + tg]);
                af[mt][1] = __float_as_uint(At[(mb + 8) * GSTRIDE + kk + tg]);
                af[mt][2] = __float_as_uint(At[mb * GSTRIDE + kk + 4 + tg]);
                af[mt][3] = __float_as_uint(At[(mb + 8) * GSTRIDE + kk + 4 + tg]);
            }
#pragma unroll
            for (int nt = 0; nt < 8; nt++) {
                const int nb = wn + nt * 8 + g;
                bf[nt][0] = __float_as_uint(Bt[nb * GSTRIDE + kk + tg]);
                bf[nt][1] = __float_as_uint(Bt[nb * GSTRIDE + kk + 4 + tg]);
            }
#pragma unroll
            for (int mt = 0; mt < 4; mt++)
#pragma unroll
                for (int nt = 0; nt < 8; nt++)
                    mma_tf32(acc[mt][nt], af[mt], bf[nt]);
        }

        if (t + GSTAGES - 1 < T) {
            const int tn = t + GSTAGES - 1;
            const int ko = tn * 32;
            const int so = tn % GSTAGES;
#pragma unroll
            for (int c = 0; c < 4; c++) cp16(dAo[c] + so * ASTGB, aP[c] + ko, true);
#pragma unroll
            for (int c = 0; c < 8; c++) cp16(dBo[c] + so * BSTGB, wP[c] + ko, wv[c]);
        }
        asm volatile("cp.async.commit_group;\n");
    }

    // epilogue
    float* Cz = C + (size_t)z * cstride;
#pragma unroll
    for (int mt = 0; mt < 4; mt++) {
        const int r0 = m0 + wm + mt * 16 + g;
        const int r1 = r0 + 8;
#pragma unroll
        for (int nt = 0; nt < 8; nt++) {
            const int c0 = e0 + wn + nt * 8 + tg * 2;
#pragma unroll
            for (int jj = 0; jj < 2; jj++) {
                const int c = c0 + jj;
                if (c < E) {
                    float va = acc[mt][nt][jj];
                    float vb = acc[mt][nt][2 + jj];
                    if (epi == 1) {
                        const float bv = bias[c];
                        va += bv;
                        va = fmaxf(va, 0.f) + log1pf(__expf(-fabsf(va)));
                        vb += bv;
                        vb = fmaxf(vb, 0.f) + log1pf(__expf(-fabsf(vb)));
                    }
                    Cz[(size_t)r0 * ldc + c] = va;
                    Cz[(size_t)r1 * ldc + c] = vb;
                }
            }
        }
    }
}

// ---------------- split-K reduce for x_proj ----------------
__global__ __launch_bounds__(256) void reduce_dbl() {
    const int idx = blockIdx.x * 256 + threadIdx.x;
    if (idx >= MTOT * DBLW) return;
    float s = 0.f;
#pragma unroll
    for (int p = 0; p < SPLITK; p++) s += g_dblp[(size_t)p * MTOT * DBLW + idx];
    g_dbl[idx] = rnd_tf32(s);
}

// ---------------- conv+silu ----------------
__global__ __launch_bounds__(256) void conv_silu_kernel(const float* __restrict__ conv_w,
                                                        const float* __restrict__ conv_b) {
    const int t = blockIdx.x * 256 + threadIdx.x;
    const int nd4 = DIN / 4;
    const int d0 = (t % nd4) * 4;
    const int m0 = (t / nd4) * 4;
    if (m0 >= MTOT) return;
    const int l0 = m0 % LL;
    const int b = m0 / LL;

    float4 xr[7];
#pragma unroll
    for (int j = 0; j < 7; j++) {
        const int ls = l0 - 3 + j;
        if (ls >= 0)
            xr[j] = *(const float4*)(g_xz + ((size_t)(b * LL + ls)) * (2 * DIN) + d0);
        else
            xr[j] = make_float4(0.f, 0.f, 0.f, 0.f);
    }
    float4 w0 = *(const float4*)(conv_w + (d0 + 0) * 4);
    float4 w1 = *(const float4*)(conv_w + (d0 + 1) * 4);
    float4 w2 = *(const float4*)(conv_w + (d0 + 2) * 4);
    float4 w3 = *(const float4*)(conv_w + (d0 + 3) * 4);
    const float4 bv = *(const float4*)(conv_b + d0);

#pragma unroll
    for (int i = 0; i < 4; i++) {
        float4 acc;
        acc.x = bv.x + w0.x * xr[i].x + w0.y * xr[i+1].x + w0.z * xr[i+2].x + w0.w * xr[i+3].x;
        acc.y = bv.y + w1.x * xr[i].y + w1.y * xr[i+1].y + w1.z * xr[i+2].y + w1.w * xr[i+3].y;
        acc.z = bv.z + w2.x * xr[i].z + w2.y * xr[i+1].z + w2.z * xr[i+2].z + w2.w * xr[i+3].z;
        acc.w = bv.w + w3.x * xr[i].w + w3.y * xr[i+1].w + w3.z * xr[i+2].w + w3.w * xr[i+3].w;
        float4 o;
        o.x = rnd_tf32(acc.x / (1.f + __expf(-acc.x)));
        o.y = rnd_tf32(acc.y / (1.f + __expf(-acc.y)));
        o.z = rnd_tf32(acc.z / (1.f + __expf(-acc.z)));
        o.w = rnd_tf32(acc.w / (1.f + __expf(-acc.w)));
        *(float4*)(g_xconv + ((size_t)(m0 + i)) * DIN + d0) = o;
    }
}

// ---------------- chunked selective scan ----------------
__global__ __launch_bounds__(128) void scan_pass1(const float* __restrict__ A_log) {
    const int b = blockIdx.z;
    const int s = blockIdx.y;
    const int d = blockIdx.x * 128 + threadIdx.x;
    const int tid = threadIdx.x;
    const int l0 = s * SEGL;

    float A[NS];
#pragma unroll
    for (int n = 0; n < NS; n++) A[n] = -__expf(A_log[d * NS + n]);

    float p[NS], h[NS];
#pragma unroll
    for (int n = 0; n < NS; n++) { p[n] = 1.f; h[n] = 0.f; }

    __shared__ float sB[SEGL][NS];
    for (int i = tid; i < SEGL * NS; i += 128) {
        const int ll = i >> 3;
        const int n = i & 7;
        sB[ll][n] = g_dbl[((size_t)(b * LL + l0 + ll)) * DBLW + RR + n];
    }
    __syncthreads();

    for (int j = 0; j < SEGL; j++) {
        const size_t idx = ((size_t)(b * LL + l0 + j)) * DIN + d;
        const float dtv = g_dt[idx];
        const float xv = g_xconv[idx];
        const float dtx = dtv * xv;
#pragma unroll
        for (int n = 0; n < NS; n++) {
            const float da = __expf(dtv * A[n]);
            p[n] *= da;
            h[n] = da * h[n] + dtx * sB[j][n];
        }
    }
#pragma unroll
    for (int n = 0; n < NS; n++) {
        const size_t o = ((size_t)((b * SEG + s) * NS + n)) * DIN + d;
        g_segA[o] = p[n];
        g_segB[o] = h[n];
    }
}

__global__ __launch_bounds__(256) void scan_pass2() {
    const int gidx = blockIdx.x * 256 + threadIdx.x;
    if (gidx >= BB * DIN) return;
    const int b = gidx / DIN;
    const int d = gidx % DIN;
    float h[NS];
#pragma unroll
    for (int n = 0; n < NS; n++) h[n] = 0.f;
    for (int s = 0; s < SEG; s++) {
#pragma unroll
        for (int n = 0; n < NS; n++) {
            const size_t o = ((size_t)((b * SEG + s) * NS + n)) * DIN + d;
            g_hin[o] = h[n];
            h[n] = g_segA[o] * h[n] + g_segB[o];
        }
    }
}

__global__ __launch_bounds__(128) void scan_pass3(const float* __restrict__ A_log,
                                                  const float* __restrict__ D_skip) {
    const int b = blockIdx.z;
    const int s = blockIdx.y;
    const int d = blockIdx.x * 128 + threadIdx.x;
    const int tid = threadIdx.x;
    const int l0 = s * SEGL;

    float A[NS];
#pragma unroll
    for (int n = 0; n < NS; n++) A[n] = -__expf(A_log[d * NS + n]);
    const float dsk = D_skip[d];

    float h[NS];
#pragma unroll
    for (int n = 0; n < NS; n++)
        h[n] = g_hin[((size_t)((b * SEG + s) * NS + n)) * DIN + d];

    __shared__ float sB[SEGL][NS];
    __shared__ float sC[SEGL][NS];
    for (int i = tid; i < SEGL * NS * 2; i += 128) {
        const int ll = i >> 4;
        const int c = i & 15;
        const float v = g_dbl[((size_t)(b * LL + l0 + ll)) * DBLW + RR + c];
        if (c < NS) sB[ll][c] = v;
        else        sC[ll][c - NS] = v;
    }
    __syncthreads();

    for (int j = 0; j < SEGL; j++) {
        const size_t idx = ((size_t)(b * LL + l0 + j)) * DIN + d;
        const float dtv = g_dt[idx];
        const float xv = g_xconv[idx];
        const float dtx = dtv * xv;
        float yv = 0.f;
#pragma unroll
        for (int n = 0; n < NS; n++) {
            const float da = __expf(dtv * A[n]);
            h[n] = da * h[n] + dtx * sB[j][n];
            yv += h[n] * sC[j][n];
        }
        const float z = g_xz[((size_t)(b * LL + l0 + j)) * (2 * DIN) + DIN + d];
        const float sz = z / (1.f + __expf(-z));
        g_y[idx] = rnd_tf32((yv + dsk * xv) * sz);
    }
}

// ---------------- launch ----------------
extern "C" void kernel_launch(void* const* d_in, const int* in_sizes, int n_in,
                              void* d_out, int out_size) {
    const float* hidden = (const float*)d_in[0];
    const float* norm_w = (const float*)d_in[1];
    const float* in_proj_w = (const float*)d_in[2];
    const float* conv_w = (const float*)d_in[3];
    const float* conv_b = (const float*)d_in[4];
    const float* x_proj_w = (const float*)d_in[5];
    const float* dt_proj_w = (const float*)d_in[6];
    const float* dt_proj_b = (const float*)d_in[7];
    const float* A_log = (const float*)d_in[8];
    const float* D_skip = (const float*)d_in[9];
    const float* out_proj_w = (const float*)d_in[10];
    float* out = (float*)d_out;

    float *p_xnorm, *p_xz, *p_xconv, *p_dbl, *p_dblp, *p_dt, *p_y;
    float *p_w_in, *p_w_x, *p_w_dt, *p_w_out;
    cudaGetSymbolAddress((void**)&p_xnorm, g_xnorm);
    cudaGetSymbolAddress((void**)&p_xz, g_xz);
    cudaGetSymbolAddress((void**)&p_xconv, g_xconv);
    cudaGetSymbolAddress((void**)&p_dbl, g_dbl);
    cudaGetSymbolAddress((void**)&p_dblp, g_dblp);
    cudaGetSymbolAddress((void**)&p_dt, g_dt);
    cudaGetSymbolAddress((void**)&p_y, g_y);
    cudaGetSymbolAddress((void**)&p_w_in, g_w_in);
    cudaGetSymbolAddress((void**)&p_w_x, g_w_x);
    cudaGetSymbolAddress((void**)&p_w_dt, g_w_dt);
    cudaGetSymbolAddress((void**)&p_w_out, g_w_out);

    cudaFuncSetAttribute(gemm_tf32, cudaFuncAttributeMaxDynamicSharedMemorySize, GSMEM);

    const int M = MTOT;

    // 0. weights -> tf32
    {
        const int total4 = (NWI + NWX + NWDT + NWO) / 4;
        cvt_weights<<<(total4 + 255) / 256, 256>>>((const float4*)in_proj_w,
                                                   (const float4*)x_proj_w,
                                                   (const float4*)dt_proj_w,
                                                   (const float4*)out_proj_w);
    }

    // 1. RMSNorm
    rmsnorm_kernel<<<M, 256>>>(hidden, norm_w);

    // 2. in_proj: xz[M,2048]
    {
        dim3 grid(2 * DIN / 256, M / 128, 1);
        gemm_tf32<<<grid, 256, GSMEM>>>(p_xnorm, DD, p_w_in, DD,
                                        p_xz, 2 * DIN, 0, DD, 2 * DIN, nullptr, 0);
    }

    // 3. conv + silu
    {
        const int total = (MTOT / 4) * (DIN / 4);
        conv_silu_kernel<<<(total + 255) / 256, 256>>>(conv_w, conv_b);
    }

    // 4. x_proj split-K
    {
        dim3 grid(1, M / 128, SPLITK);
        gemm_tf32<<<grid, 256, GSMEM>>>(p_xconv, DIN, p_w_x, DIN,
                                        p_dblp, DBLW, (size_t)MTOT * DBLW,
                                        DIN / SPLITK, DBLW, nullptr, 0);
        reduce_dbl<<<(MTOT * DBLW + 255) / 256, 256>>>();
    }

    // 5. dt_proj + bias + softplus
    {
        dim3 grid(DIN / 256, M / 128, 1);
        gemm_tf32<<<grid, 256, GSMEM>>>(p_dbl, DBLW, p_w_dt, RR,
                                        p_dt, DIN, 0, RR, DIN, dt_proj_b, 1);
    }

    // 6. selective scan
    {
        dim3 grid1(DIN / 128, SEG, BB);
        scan_pass1<<<grid1, 128>>>(A_log);
        scan_pass2<<<(BB * DIN + 255) / 256, 256>>>();
        scan_pass3<<<grid1, 128>>>(A_log, D_skip);
    }

    // 7. out_proj
    {
        dim3 grid(DD / 256, M / 128, 1);
        gemm_tf32<<<grid, 256, GSMEM>>>(p_y, DIN, p_w_out, DIN,
                                        out, DD, 0, DIN, DD, nullptr, 0);
    }
}

// round 7
// speedup vs baseline: 1.0261x; 1.0261x over previous
#include <cuda_runtime.h>
#include <math.h>
#include <stdint.h>

#define BB 4
#define LL 2048
#define DD 1024
#define DIN 1024
#define NS 8
#define RR 64
#define DBLW 80
#define SEG 16
#define SEGL 128
#define MTOT (BB*LL)
#define SPLITK 4

// ---------------- scratch ----------------
__device__ float g_xnorm[MTOT*DD];
__device__ float g_xz[MTOT*2*DIN];
__device__ float g_xconv[MTOT*DIN];
__device__ float g_dbl[MTOT*DBLW];
__device__ float g_dblp[SPLITK*MTOT*DBLW];
__device__ float g_dt[MTOT*DIN];
__device__ float g_y[MTOT*DIN];
__device__ float g_segA[BB*SEG*NS*DIN];
__device__ float g_segB[BB*SEG*NS*DIN];
__device__ float g_hin[BB*SEG*NS*DIN];
__device__ float g_w_in[2*DIN*DD];
__device__ float g_w_x[DBLW*DIN];
__device__ float g_w_dt[DIN*RR];
__device__ float g_w_out[DD*DIN];

// ---------------- helpers ----------------
__device__ __forceinline__ float rnd_tf32(float f) {
    uint32_t u;
    asm("cvt.rna.tf32.f32 %0, %1;" : "=r"(u) : "f"(f));
    return __uint_as_float(u);
}

__device__ __forceinline__ void mma_tf32(float c[4], const uint32_t a[4], const uint32_t b[2]) {
    asm volatile(
        "mma.sync.aligned.m16n8k8.row.col.f32.tf32.tf32.f32 "
        "{%0,%1,%2,%3}, {%4,%5,%6,%7}, {%8,%9}, {%0,%1,%2,%3};"
        : "+f"(c[0]), "+f"(c[1]), "+f"(c[2]), "+f"(c[3])
        : "r"(a[0]), "r"(a[1]), "r"(a[2]), "r"(a[3]), "r"(b[0]), "r"(b[1]));
}

__device__ __forceinline__ void cp16(uint32_t dst, const void* src, bool v) {
    int sz = v ? 16 : 0;
    asm volatile("cp.async.cg.shared.global [%0], [%1], 16, %2;\n"
                 :: "r"(dst), "l"(src), "r"(sz));
}

// ---------------- weight convert ----------------
#define NWI (2*DIN*DD)
#define NWX (DBLW*DIN)
#define NWDT (DIN*RR)
#define NWO (DD*DIN)
__global__ __launch_bounds__(256) void cvt_weights(const float4* __restrict__ iw,
                                                   const float4* __restrict__ xw,
                                                   const float4* __restrict__ dw,
                                                   const float4* __restrict__ ow) {
    int i = blockIdx.x * 256 + threadIdx.x;
    const float4* src;
    float4* dst;
    if (i < NWI/4) { src = iw + i; dst = (float4*)g_w_in + i; }
    else if ((i -= NWI/4) < NWX/4) { src = xw + i; dst = (float4*)g_w_x + i; }
    else if ((i -= NWX/4) < NWDT/4) { src = dw + i; dst = (float4*)g_w_dt + i; }
    else if ((i -= NWDT/4) < NWO/4) { src = ow + i; dst = (float4*)g_w_out + i; }
    else return;
    float4 v = *src;
    v.x = rnd_tf32(v.x); v.y = rnd_tf32(v.y);
    v.z = rnd_tf32(v.z); v.w = rnd_tf32(v.w);
    *dst = v;
}

// ---------------- RMSNorm ----------------
__global__ __launch_bounds__(256) void rmsnorm_kernel(const float* __restrict__ x,
                                                      const float* __restrict__ w) {
    const int row = blockIdx.x;
    const float4 v = *((const float4*)(x + (size_t)row * DD) + threadIdx.x);
    float ss = v.x*v.x + v.y*v.y + v.z*v.z + v.w*v.w;
#pragma unroll
    for (int o = 16; o > 0; o >>= 1) ss += __shfl_xor_sync(0xffffffffu, ss, o);
    __shared__ float red[8];
    if ((threadIdx.x & 31) == 0) red[threadIdx.x >> 5] = ss;
    __syncthreads();
    float tot = 0.f;
#pragma unroll
    for (int i = 0; i < 8; i++) tot += red[i];
    const float sc = rsqrtf(tot * (1.f / DD) + 1e-5f);
    const float4 wv = *((const float4*)w + threadIdx.x);
    float4 o;
    o.x = rnd_tf32(v.x * sc * wv.x);
    o.y = rnd_tf32(v.y * sc * wv.y);
    o.z = rnd_tf32(v.z * sc * wv.z);
    o.w = rnd_tf32(v.w * sc * wv.w);
    *((float4*)(g_xnorm + (size_t)row * DD) + threadIdx.x) = o;
}

// ---------------- TF32 GEMM: BM=BN=128, BK=32, 128 threads, 4 warps 64x64 ----------------
#define GSTAGES 3
#define GSTRIDE 36
#define STGF (128*GSTRIDE)
#define STGB (STGF*4)
#define GSMEM (2*GSTAGES*STGB)   // 110592 bytes

__global__ __launch_bounds__(128, 2) void gemm_tf32(
    const float* __restrict__ A, int lda,
    const float* __restrict__ W, int ldw,
    float* __restrict__ C, int ldc, size_t cstride,
    int K, int E,
    const float* __restrict__ bias, int epi)
{
    extern __shared__ float smem[];
    float* sA = smem;
    float* sB = smem + GSTAGES * STGF;

    const int tid = threadIdx.x;
    const int lane = tid & 31;
    const int wid = tid >> 5;
    const int m0 = blockIdx.y * 128;
    const int e0 = blockIdx.x * 128;
    const int z = blockIdx.z;
    const int wm = (wid & 1) * 64;
    const int wn = (wid >> 1) * 64;

    // producer: 128 threads, 16 rows x 8 quads per pass, 8 passes per matrix
    const int prow = tid >> 3;        // 0..15
    const int pk = (tid & 7) * 4;     // 0..28

    const uint32_t sAu = (uint32_t)__cvta_generic_to_shared(sA);
    const uint32_t sBu = (uint32_t)__cvta_generic_to_shared(sB);

    const float* aP[8];
    uint32_t dAo[8];
    const float* wP[8];
    bool wv[8];
    uint32_t dBo[8];
#pragma unroll
    for (int c = 0; c < 8; c++) {
        const int r = prow + 16 * c;
        aP[c] = A + (size_t)(m0 + r) * lda + (size_t)z * K + pk;
        dAo[c] = sAu + (r * GSTRIDE + pk) * 4;
        const int er = e0 + r;
        wv[c] = er < E;
        wP[c] = W + (size_t)(wv[c] ? er : 0) * ldw + (size_t)z * K + pk;
        dBo[c] = sBu + (r * GSTRIDE + pk) * 4;
    }

    float acc[4][8][4];
#pragma unroll
    for (int i = 0; i < 4; i++)
#pragma unroll
        for (int j = 0; j < 8; j++)
#pragma unroll
            for (int l = 0; l < 4; l++) acc[i][j][l] = 0.f;

    const int T = K / 32;

#pragma unroll
    for (int p = 0; p < GSTAGES - 1; p++) {
        if (p < T) {
            const int ko = p * 32;
#pragma unroll
            for (int c = 0; c < 8; c++) cp16(dAo[c] + p * STGB, aP[c] + ko, true);
#pragma unroll
            for (int c = 0; c < 8; c++) cp16(dBo[c] + p * STGB, wP[c] + ko, wv[c]);
        }
        asm volatile("cp.async.commit_group;\n");
    }

    const int g = lane >> 2;
    const int tg = lane & 3;

    for (int t = 0; t < T; t++) {
        asm volatile("cp.async.wait_group 1;\n");
        __syncthreads();

        // issue next-stage loads BEFORE compute so they overlap the MMAs
        {
            const int tn = t + GSTAGES - 1;
            if (tn < T) {
                const int ko = tn * 32;
                const int so = tn % GSTAGES;
#pragma unroll
                for (int c = 0; c < 8; c++) cp16(dAo[c] + so * STGB, aP[c] + ko, true);
#pragma unroll
                for (int c = 0; c < 8; c++) cp16(dBo[c] + so * STGB, wP[c] + ko, wv[c]);
            }
            asm volatile("cp.async.commit_group;\n");
        }

        const int stg = t % GSTAGES;
        const float* At = sA + stg * STGF;
        const float* Bt = sB + stg * STGF;

#pragma unroll
        for (int ks = 0; ks < 4; ks++) {
            const int kk = ks * 8;
            uint32_t af[4][4];
            uint32_t bf[8][2];
#pragma unroll
            for (int mt = 0; mt < 4; mt++) {
                const int mb = wm + mt * 16 + g;
                af[mt][0] = __float_as_uint(At[mb * GSTRIDE + kk + tg]);
                af[mt][1] = __float_as_uint(At[(mb + 8) * GSTRIDE + kk + tg]);
                af[mt][2] = __float_as_uint(At[mb * GSTRIDE + kk + 4 + tg]);
                af[mt][3] = __float_as_uint(At[(mb + 8) * GSTRIDE + kk + 4 + tg]);
            }
#pragma unroll
            for (int nt = 0; nt < 8; nt++) {
                const int nb = wn + nt * 8 + g;
                bf[nt][0] = __float_as_uint(Bt[nb * GSTRIDE + kk + tg]);
                bf[nt][1] = __float_as_uint(Bt[nb * GSTRIDE + kk + 4 + tg]);
            }
#pragma unroll
            for (int mt = 0; mt < 4; mt++)
#pragma unroll
                for (int nt = 0; nt < 8; nt++)
                    mma_tf32(acc[mt][nt], af[mt], bf[nt]);
        }
    }

    // epilogue
    float* Cz = C + (size_t)z * cstride;
#pragma unroll
    for (int mt = 0; mt < 4; mt++) {
        const int r0 = m0 + wm + mt * 16 + g;
        const int r1 = r0 + 8;
#pragma unroll
        for (int nt = 0; nt < 8; nt++) {
            const int c0 = e0 + wn + nt * 8 + tg * 2;
#pragma unroll
            for (int jj = 0; jj < 2; jj++) {
                const int c = c0 + jj;
                if (c < E) {
                    float va = acc[mt][nt][jj];
                    float vb = acc[mt][nt][2 + jj];
                    if (epi == 1) {
                        const float bv = bias[c];
                        va += bv;
                        va = fmaxf(va, 0.f) + log1pf(__expf(-fabsf(va)));
                        vb += bv;
                        vb = fmaxf(vb, 0.f) + log1pf(__expf(-fabsf(vb)));
                    }
                    Cz[(size_t)r0 * ldc + c] = va;
                    Cz[(size_t)r1 * ldc + c] = vb;
                }
            }
        }
    }
}

// ---------------- split-K reduce for x_proj ----------------
__global__ __launch_bounds__(256) void reduce_dbl() {
    const int idx = blockIdx.x * 256 + threadIdx.x;
    if (idx >= MTOT * DBLW) return;
    float s = 0.f;
#pragma unroll
    for (int p = 0; p < SPLITK; p++) s += g_dblp[(size_t)p * MTOT * DBLW + idx];
    g_dbl[idx] = rnd_tf32(s);
}

// ---------------- conv+silu ----------------
__global__ __launch_bounds__(256) void conv_silu_kernel(const float* __restrict__ conv_w,
                                                        const float* __restrict__ conv_b) {
    const int t = blockIdx.x * 256 + threadIdx.x;
    const int nd4 = DIN / 4;
    const int d0 = (t % nd4) * 4;
    const int m0 = (t / nd4) * 4;
    if (m0 >= MTOT) return;
    const int l0 = m0 % LL;
    const int b = m0 / LL;

    float4 xr[7];
#pragma unroll
    for (int j = 0; j < 7; j++) {
        const int ls = l0 - 3 + j;
        if (ls >= 0)
            xr[j] = *(const float4*)(g_xz + ((size_t)(b * LL + ls)) * (2 * DIN) + d0);
        else
            xr[j] = make_float4(0.f, 0.f, 0.f, 0.f);
    }
    float4 w0 = *(const float4*)(conv_w + (d0 + 0) * 4);
    float4 w1 = *(const float4*)(conv_w + (d0 + 1) * 4);
    float4 w2 = *(const float4*)(conv_w + (d0 + 2) * 4);
    float4 w3 = *(const float4*)(conv_w + (d0 + 3) * 4);
    const float4 bv = *(const float4*)(conv_b + d0);

#pragma unroll
    for (int i = 0; i < 4; i++) {
        float4 acc;
        acc.x = bv.x + w0.x * xr[i].x + w0.y * xr[i+1].x + w0.z * xr[i+2].x + w0.w * xr[i+3].x;
        acc.y = bv.y + w1.x * xr[i].y + w1.y * xr[i+1].y + w1.z * xr[i+2].y + w1.w * xr[i+3].y;
        acc.z = bv.z + w2.x * xr[i].z + w2.y * xr[i+1].z + w2.z * xr[i+2].z + w2.w * xr[i+3].z;
        acc.w = bv.w + w3.x * xr[i].w + w3.y * xr[i+1].w + w3.z * xr[i+2].w + w3.w * xr[i+3].w;
        float4 o;
        o.x = rnd_tf32(acc.x / (1.f + __expf(-acc.x)));
        o.y = rnd_tf32(acc.y / (1.f + __expf(-acc.y)));
        o.z = rnd_tf32(acc.z / (1.f + __expf(-acc.z)));
        o.w = rnd_tf32(acc.w / (1.f + __expf(-acc.w)));
        *(float4*)(g_xconv + ((size_t)(m0 + i)) * DIN + d0) = o;
    }
}

// ---------------- chunked selective scan ----------------
__global__ __launch_bounds__(128) void scan_pass1(const float* __restrict__ A_log) {
    const int b = blockIdx.z;
    const int s = blockIdx.y;
    const int d = blockIdx.x * 128 + threadIdx.x;
    const int tid = threadIdx.x;
    const int l0 = s * SEGL;

    float A[NS];
#pragma unroll
    for (int n = 0; n < NS; n++) A[n] = -__expf(A_log[d * NS + n]);

    float p[NS], h[NS];
#pragma unroll
    for (int n = 0; n < NS; n++) { p[n] = 1.f; h[n] = 0.f; }

    __shared__ float sB[SEGL][NS];
    for (int i = tid; i < SEGL * NS; i += 128) {
        const int ll = i >> 3;
        const int n = i & 7;
        sB[ll][n] = g_dbl[((size_t)(b * LL + l0 + ll)) * DBLW + RR + n];
    }
    __syncthreads();

    for (int j = 0; j < SEGL; j++) {
        const size_t idx = ((size_t)(b * LL + l0 + j)) * DIN + d;
        const float dtv = g_dt[idx];
        const float xv = g_xconv[idx];
        const float dtx = dtv * xv;
#pragma unroll
        for (int n = 0; n < NS; n++) {
            const float da = __expf(dtv * A[n]);
            p[n] *= da;
            h[n] = da * h[n] + dtx * sB[j][n];
        }
    }
#pragma unroll
    for (int n = 0; n < NS; n++) {
        const size_t o = ((size_t)((b * SEG + s) * NS + n)) * DIN + d;
        g_segA[o] = p[n];
        g_segB[o] = h[n];
    }
}

__global__ __launch_bounds__(256) void scan_pass2() {
    const int gidx = blockIdx.x * 256 + threadIdx.x;
    if (gidx >= BB * DIN) return;
    const int b = gidx / DIN;
    const int d = gidx % DIN;
    float h[NS];
#pragma unroll
    for (int n = 0; n < NS; n++) h[n] = 0.f;
    for (int s = 0; s < SEG; s++) {
#pragma unroll
        for (int n = 0; n < NS; n++) {
            const size_t o = ((size_t)((b * SEG + s) * NS + n)) * DIN + d;
            g_hin[o] = h[n];
            h[n] = g_segA[o] * h[n] + g_segB[o];
        }
    }
}

__global__ __launch_bounds__(128) void scan_pass3(const float* __restrict__ A_log,
                                                  const float* __restrict__ D_skip) {
    const int b = blockIdx.z;
    const int s = blockIdx.y;
    const int d = blockIdx.x * 128 + threadIdx.x;
    const int tid = threadIdx.x;
    const int l0 = s * SEGL;

    float A[NS];
#pragma unroll
    for (int n = 0; n < NS; n++) A[n] = -__expf(A_log[d * NS + n]);
    const float dsk = D_skip[d];

    float h[NS];
#pragma unroll
    for (int n = 0; n < NS; n++)
        h[n] = g_hin[((size_t)((b * SEG + s) * NS + n)) * DIN + d];

    __shared__ float sB[SEGL][NS];
    __shared__ float sC[SEGL][NS];
    for (int i = tid; i < SEGL * NS * 2; i += 128) {
        const int ll = i >> 4;
        const int c = i & 15;
        const float v = g_dbl[((size_t)(b * LL + l0 + ll)) * DBLW + RR + c];
        if (c < NS) sB[ll][c] = v;
        else        sC[ll][c - NS] = v;
    }
    __syncthreads();

    for (int j = 0; j < SEGL; j++) {
        const size_t idx = ((size_t)(b * LL + l0 + j)) * DIN + d;
        const float dtv = g_dt[idx];
        const float xv = g_xconv[idx];
        const float dtx = dtv * xv;
        float yv = 0.f;
#pragma unroll
        for (int n = 0; n < NS; n++) {
            const float da = __expf(dtv * A[n]);
            h[n] = da * h[n] + dtx * sB[j][n];
            yv += h[n] * sC[j][n];
        }
        const float z = g_xz[((size_t)(b * LL + l0 + j)) * (2 * DIN) + DIN + d];
        const float sz = z / (1.f + __expf(-z));
        g_y[idx] = rnd_tf32((yv + dsk * xv) * sz);
    }
}

// ---------------- launch ----------------
extern "C" void kernel_launch(void* const* d_in, const int* in_sizes, int n_in,
                              void* d_out, int out_size) {
    const float* hidden = (const float*)d_in[0];
    const float* norm_w = (const float*)d_in[1];
    const float* in_proj_w = (const float*)d_in[2];
    const float* conv_w = (const float*)d_in[3];
    const float* conv_b = (const float*)d_in[4];
    const float* x_proj_w = (const float*)d_in[5];
    const float* dt_proj_w = (const float*)d_in[6];
    const float* dt_proj_b = (const float*)d_in[7];
    const float* A_log = (const float*)d_in[8];
    const float* D_skip = (const float*)d_in[9];
    const float* out_proj_w = (const float*)d_in[10];
    float* out = (float*)d_out;

    float *p_xnorm, *p_xz, *p_xconv, *p_dbl, *p_dblp, *p_dt, *p_y;
    float *p_w_in, *p_w_x, *p_w_dt, *p_w_out;
    cudaGetSymbolAddress((void**)&p_xnorm, g_xnorm);
    cudaGetSymbolAddress((void**)&p_xz, g_xz);
    cudaGetSymbolAddress((void**)&p_xconv, g_xconv);
    cudaGetSymbolAddress((void**)&p_dbl, g_dbl);
    cudaGetSymbolAddress((void**)&p_dblp, g_dblp);
    cudaGetSymbolAddress((void**)&p_dt, g_dt);
    cudaGetSymbolAddress((void**)&p_y, g_y);
    cudaGetSymbolAddress((void**)&p_w_in, g_w_in);
    cudaGetSymbolAddress((void**)&p_w_x, g_w_x);
    cudaGetSymbolAddress((void**)&p_w_dt, g_w_dt);
    cudaGetSymbolAddress((void**)&p_w_out, g_w_out);

    cudaFuncSetAttribute(gemm_tf32, cudaFuncAttributeMaxDynamicSharedMemorySize, GSMEM);

    const int M = MTOT;

    // 0. weights -> tf32
    {
        const int total4 = (NWI + NWX + NWDT + NWO) / 4;
        cvt_weights<<<(total4 + 255) / 256, 256>>>((const float4*)in_proj_w,
                                                   (const float4*)x_proj_w,
                                                   (const float4*)dt_proj_w,
                                                   (const float4*)out_proj_w);
    }

    // 1. RMSNorm
    rmsnorm_kernel<<<M, 256>>>(hidden, norm_w);

    // 2. in_proj: xz[M,2048]
    {
        dim3 grid(2 * DIN / 128, M / 128, 1);
        gemm_tf32<<<grid, 128, GSMEM>>>(p_xnorm, DD, p_w_in, DD,
                                        p_xz, 2 * DIN, 0, DD, 2 * DIN, nullptr, 0);
    }

    // 3. conv + silu
    {
        const int total = (MTOT / 4) * (DIN / 4);
        conv_silu_kernel<<<(total + 255) / 256, 256>>>(conv_w, conv_b);
    }

    // 4. x_proj split-K
    {
        dim3 grid(1, M / 128, SPLITK);
        gemm_tf32<<<grid, 128, GSMEM>>>(p_xconv, DIN, p_w_x, DIN,
                                        p_dblp, DBLW, (size_t)MTOT * DBLW,
                                        DIN / SPLITK, DBLW, nullptr, 0);
        reduce_dbl<<<(MTOT * DBLW + 255) / 256, 256>>>();
    }

    // 5. dt_proj + bias + softplus
    {
        dim3 grid(DIN / 128, M / 128, 1);
        gemm_tf32<<<grid, 128, GSMEM>>>(p_dbl, DBLW, p_w_dt, RR,
                                        p_dt, DIN, 0, RR, DIN, dt_proj_b, 1);
    }

    // 6. selective scan
    {
        dim3 grid1(DIN / 128, SEG, BB);
        scan_pass1<<<grid1, 128>>>(A_log);
        scan_pass2<<<(BB * DIN + 255) / 256, 256>>>();
        scan_pass3<<<grid1, 128>>>(A_log, D_skip);
    }

    // 7. out_proj
    {
        dim3 grid(DD / 128, M / 128, 1);
        gemm_tf32<<<grid, 128, GSMEM>>>(p_y, DIN, p_w_out, DIN,
                                        out, DD, 0, DIN, DD, nullptr, 0);
    }
}

// round 8
// speedup vs baseline: 1.1451x; 1.1160x over previous
#include <cuda_runtime.h>
#include <math.h>
#include <stdint.h>

#define BB 4
#define LL 2048
#define DD 1024
#define DIN 1024
#define NS 8
#define RR 64
#define DBLW 80
#define SEG 32
#define SEGL (LL/SEG)     // 64
#define MTOT (BB*LL)
#define SPLITK 4

// ---------------- scratch ----------------
__device__ float g_xnorm[MTOT*DD];
__device__ float g_xz[MTOT*2*DIN];
__device__ float g_xconv[MTOT*DIN];
__device__ float g_dbl[MTOT*DBLW];
__device__ float g_dblp[SPLITK*MTOT*DBLW];
__device__ float g_dt[MTOT*DIN];
__device__ float g_y[MTOT*DIN];
__device__ float g_segA[BB*SEG*NS*DIN];
__device__ float g_segB[BB*SEG*NS*DIN];
__device__ float g_hin[BB*SEG*NS*DIN];
__device__ float g_w_in[2*DIN*DD];
__device__ float g_w_x[DBLW*DIN];
__device__ float g_w_dt[DIN*RR];
__device__ float g_w_out[DD*DIN];

// ---------------- helpers ----------------
__device__ __forceinline__ float rnd_tf32(float f) {
    uint32_t u;
    asm("cvt.rna.tf32.f32 %0, %1;" : "=r"(u) : "f"(f));
    return __uint_as_float(u);
}

__device__ __forceinline__ void mma_tf32(float c[4], const uint32_t a[4], const uint32_t b[2]) {
    asm volatile(
        "mma.sync.aligned.m16n8k8.row.col.f32.tf32.tf32.f32 "
        "{%0,%1,%2,%3}, {%4,%5,%6,%7}, {%8,%9}, {%0,%1,%2,%3};"
        : "+f"(c[0]), "+f"(c[1]), "+f"(c[2]), "+f"(c[3])
        : "r"(a[0]), "r"(a[1]), "r"(a[2]), "r"(a[3]), "r"(b[0]), "r"(b[1]));
}

__device__ __forceinline__ void cp16(uint32_t dst, const void* src, bool v) {
    int sz = v ? 16 : 0;
    asm volatile("cp.async.cg.shared.global [%0], [%1], 16, %2;\n"
                 :: "r"(dst), "l"(src), "r"(sz));
}

// ---------------- weight convert ----------------
#define NWI (2*DIN*DD)
#define NWX (DBLW*DIN)
#define NWDT (DIN*RR)
#define NWO (DD*DIN)
__global__ __launch_bounds__(256) void cvt_weights(const float4* __restrict__ iw,
                                                   const float4* __restrict__ xw,
                                                   const float4* __restrict__ dw,
                                                   const float4* __restrict__ ow) {
    int i = blockIdx.x * 256 + threadIdx.x;
    const float4* src;
    float4* dst;
    if (i < NWI/4) { src = iw + i; dst = (float4*)g_w_in + i; }
    else if ((i -= NWI/4) < NWX/4) { src = xw + i; dst = (float4*)g_w_x + i; }
    else if ((i -= NWX/4) < NWDT/4) { src = dw + i; dst = (float4*)g_w_dt + i; }
    else if ((i -= NWDT/4) < NWO/4) { src = ow + i; dst = (float4*)g_w_out + i; }
    else return;
    float4 v = *src;
    v.x = rnd_tf32(v.x); v.y = rnd_tf32(v.y);
    v.z = rnd_tf32(v.z); v.w = rnd_tf32(v.w);
    *dst = v;
}

// ---------------- RMSNorm ----------------
__global__ __launch_bounds__(256) void rmsnorm_kernel(const float* __restrict__ x,
                                                      const float* __restrict__ w) {
    const int row = blockIdx.x;
    const float4 v = *((const float4*)(x + (size_t)row * DD) + threadIdx.x);
    float ss = v.x*v.x + v.y*v.y + v.z*v.z + v.w*v.w;
#pragma unroll
    for (int o = 16; o > 0; o >>= 1) ss += __shfl_xor_sync(0xffffffffu, ss, o);
    __shared__ float red[8];
    if ((threadIdx.x & 31) == 0) red[threadIdx.x >> 5] = ss;
    __syncthreads();
    float tot = 0.f;
#pragma unroll
    for (int i = 0; i < 8; i++) tot += red[i];
    const float sc = rsqrtf(tot * (1.f / DD) + 1e-5f);
    const float4 wv = *((const float4*)w + threadIdx.x);
    float4 o;
    o.x = rnd_tf32(v.x * sc * wv.x);
    o.y = rnd_tf32(v.y * sc * wv.y);
    o.z = rnd_tf32(v.z * sc * wv.z);
    o.w = rnd_tf32(v.w * sc * wv.w);
    *((float4*)(g_xnorm + (size_t)row * DD) + threadIdx.x) = o;
}

// ---------------- TF32 GEMM: BM=BN=128, BK=32, 256 thr, 8 warps 32x64 ----------------
#define GSTAGES 3
#define GSTRIDE 36
#define STGF (128*GSTRIDE)
#define STGB (STGF*4)
#define GSMEM (2*GSTAGES*STGB)   // 110592 bytes

__global__ __launch_bounds__(256, 2) void gemm_tf32(
    const float* __restrict__ A, int lda,
    const float* __restrict__ W, int ldw,
    float* __restrict__ C, int ldc, size_t cstride,
    int K, int E,
    const float* __restrict__ bias, int epi)
{
    extern __shared__ float smem[];
    float* sA = smem;
    float* sB = smem + GSTAGES * STGF;

    const int tid = threadIdx.x;
    const int lane = tid & 31;
    const int wid = tid >> 5;
    const int m0 = blockIdx.y * 128;
    const int e0 = blockIdx.x * 128;
    const int z = blockIdx.z;
    const int mw = (wid & 3) * 32;
    const int nw = (wid >> 2) * 64;

    const int prow = tid >> 3;        // 0..31
    const int pk = (tid & 7) * 4;     // 0..28

    const float* aP[4];
    const float* wP[4];
    bool wv[4];
    uint32_t dAo[4], dBo[4];
    const uint32_t sAu = (uint32_t)__cvta_generic_to_shared(sA);
    const uint32_t sBu = (uint32_t)__cvta_generic_to_shared(sB);
#pragma unroll
    for (int c = 0; c < 4; c++) {
        const int r = prow + 32 * c;
        aP[c] = A + (size_t)(m0 + r) * lda + (size_t)z * K + pk;
        const int er = e0 + r;
        wv[c] = er < E;
        wP[c] = W + (size_t)(wv[c] ? er : 0) * ldw + (size_t)z * K + pk;
        dAo[c] = sAu + (r * GSTRIDE + pk) * 4;
        dBo[c] = sBu + (r * GSTRIDE + pk) * 4;
    }

    float acc[2][8][4];
#pragma unroll
    for (int i = 0; i < 2; i++)
#pragma unroll
        for (int j = 0; j < 8; j++)
#pragma unroll
            for (int l = 0; l < 4; l++) acc[i][j][l] = 0.f;

    const int T = K / 32;

#pragma unroll
    for (int p = 0; p < GSTAGES - 1; p++) {
        const int ko = p * 32;
#pragma unroll
        for (int c = 0; c < 4; c++) {
            cp16(dAo[c] + p * STGB, aP[c] + ko, true);
            cp16(dBo[c] + p * STGB, wP[c] + ko, wv[c]);
        }
        asm volatile("cp.async.commit_group;\n");
    }

    const int g = lane >> 2;
    const int tg = lane & 3;

    for (int t = 0; t < T; t++) {
        asm volatile("cp.async.wait_group 1;\n");
        __syncthreads();

        // issue next-stage loads BEFORE the MMA block so they overlap compute
        {
            const int tn = t + GSTAGES - 1;
            if (tn < T) {
                const int ko = tn * 32;
                const int so = tn % GSTAGES;
#pragma unroll
                for (int c = 0; c < 4; c++) {
                    cp16(dAo[c] + so * STGB, aP[c] + ko, true);
                    cp16(dBo[c] + so * STGB, wP[c] + ko, wv[c]);
                }
            }
            asm volatile("cp.async.commit_group;\n");
        }

        const int stg = t % GSTAGES;
        const float* At = sA + stg * STGF;
        const float* Bt = sB + stg * STGF;

#pragma unroll
        for (int ks = 0; ks < 4; ks++) {
            const int kk = ks * 8;
            uint32_t af[2][4];
            uint32_t bf[8][2];
#pragma unroll
            for (int mt = 0; mt < 2; mt++) {
                const int mb = mw + mt * 16 + g;
                af[mt][0] = __float_as_uint(At[mb * GSTRIDE + kk + tg]);
                af[mt][1] = __float_as_uint(At[(mb + 8) * GSTRIDE + kk + tg]);
                af[mt][2] = __float_as_uint(At[mb * GSTRIDE + kk + 4 + tg]);
                af[mt][3] = __float_as_uint(At[(mb + 8) * GSTRIDE + kk + 4 + tg]);
            }
#pragma unroll
            for (int nt = 0; nt < 8; nt++) {
                const int nb = nw + nt * 8 + g;
                bf[nt][0] = __float_as_uint(Bt[nb * GSTRIDE + kk + tg]);
                bf[nt][1] = __float_as_uint(Bt[nb * GSTRIDE + kk + 4 + tg]);
            }
#pragma unroll
            for (int mt = 0; mt < 2; mt++)
#pragma unroll
                for (int nt = 0; nt < 8; nt++)
                    mma_tf32(acc[mt][nt], af[mt], bf[nt]);
        }
    }

    // epilogue
    float* Cz = C + (size_t)z * cstride;
#pragma unroll
    for (int mt = 0; mt < 2; mt++) {
        const int r0 = m0 + mw + mt * 16 + g;
        const int r1 = r0 + 8;
#pragma unroll
        for (int nt = 0; nt < 8; nt++) {
            const int c0 = e0 + nw + nt * 8 + tg * 2;
#pragma unroll
            for (int jj = 0; jj < 2; jj++) {
                const int c = c0 + jj;
                if (c < E) {
                    float va = acc[mt][nt][jj];
                    float vb = acc[mt][nt][2 + jj];
                    if (epi == 1) {
                        const float bv = bias[c];
                        va += bv;
                        va = fmaxf(va, 0.f) + log1pf(__expf(-fabsf(va)));
                        vb += bv;
                        vb = fmaxf(vb, 0.f) + log1pf(__expf(-fabsf(vb)));
                    }
                    Cz[(size_t)r0 * ldc + c] = va;
                    Cz[(size_t)r1 * ldc + c] = vb;
                }
            }
        }
    }
}

// ---------------- split-K reduce for x_proj ----------------
__global__ __launch_bounds__(256) void reduce_dbl() {
    const int idx = blockIdx.x * 256 + threadIdx.x;
    if (idx >= MTOT * DBLW) return;
    float s = 0.f;
#pragma unroll
    for (int p = 0; p < SPLITK; p++) s += g_dblp[(size_t)p * MTOT * DBLW + idx];
    g_dbl[idx] = rnd_tf32(s);
}

// ---------------- conv+silu: 8l x 4d per thread ----------------
__global__ __launch_bounds__(256) void conv_silu_kernel(const float* __restrict__ conv_w,
                                                        const float* __restrict__ conv_b) {
    const int t = blockIdx.x * 256 + threadIdx.x;
    const int nd4 = DIN / 4;
    const int d0 = (t % nd4) * 4;
    const int m0 = (t / nd4) * 8;
    if (m0 >= MTOT) return;
    const int l0 = m0 % LL;      // LL % 8 == 0, rows stay in one batch
    const int b = m0 / LL;

    float4 xr[11];
#pragma unroll
    for (int j = 0; j < 11; j++) {
        const int ls = l0 - 3 + j;
        if (ls >= 0)
            xr[j] = *(const float4*)(g_xz + ((size_t)(b * LL + ls)) * (2 * DIN) + d0);
        else
            xr[j] = make_float4(0.f, 0.f, 0.f, 0.f);
    }
    float4 w0 = *(const float4*)(conv_w + (d0 + 0) * 4);
    float4 w1 = *(const float4*)(conv_w + (d0 + 1) * 4);
    float4 w2 = *(const float4*)(conv_w + (d0 + 2) * 4);
    float4 w3 = *(const float4*)(conv_w + (d0 + 3) * 4);
    const float4 bv = *(const float4*)(conv_b + d0);

#pragma unroll
    for (int i = 0; i < 8; i++) {
        float4 acc;
        acc.x = bv.x + w0.x * xr[i].x + w0.y * xr[i+1].x + w0.z * xr[i+2].x + w0.w * xr[i+3].x;
        acc.y = bv.y + w1.x * xr[i].y + w1.y * xr[i+1].y + w1.z * xr[i+2].y + w1.w * xr[i+3].y;
        acc.z = bv.z + w2.x * xr[i].z + w2.y * xr[i+1].z + w2.z * xr[i+2].z + w2.w * xr[i+3].z;
        acc.w = bv.w + w3.x * xr[i].w + w3.y * xr[i+1].w + w3.z * xr[i+2].w + w3.w * xr[i+3].w;
        float4 o;
        o.x = rnd_tf32(acc.x / (1.f + __expf(-acc.x)));
        o.y = rnd_tf32(acc.y / (1.f + __expf(-acc.y)));
        o.z = rnd_tf32(acc.z / (1.f + __expf(-acc.z)));
        o.w = rnd_tf32(acc.w / (1.f + __expf(-acc.w)));
        *(float4*)(g_xconv + ((size_t)(m0 + i)) * DIN + d0) = o;
    }
}

// ---------------- chunked selective scan (SEG=32) ----------------
__global__ __launch_bounds__(128) void scan_pass1(const float* __restrict__ A_log) {
    const int b = blockIdx.z;
    const int s = blockIdx.y;
    const int d = blockIdx.x * 128 + threadIdx.x;
    const int tid = threadIdx.x;
    const int l0 = s * SEGL;

    float A[NS];
#pragma unroll
    for (int n = 0; n < NS; n++) A[n] = -__expf(A_log[d * NS + n]);

    float p[NS], h[NS];
#pragma unroll
    for (int n = 0; n < NS; n++) { p[n] = 1.f; h[n] = 0.f; }

    __shared__ float sB[SEGL][NS];
    for (int i = tid; i < SEGL * NS; i += 128) {
        const int ll = i >> 3;
        const int n = i & 7;
        sB[ll][n] = g_dbl[((size_t)(b * LL + l0 + ll)) * DBLW + RR + n];
    }
    __syncthreads();

    for (int j = 0; j < SEGL; j++) {
        const size_t idx = ((size_t)(b * LL + l0 + j)) * DIN + d;
        const float dtv = g_dt[idx];
        const float xv = g_xconv[idx];
        const float dtx = dtv * xv;
#pragma unroll
        for (int n = 0; n < NS; n++) {
            const float da = __expf(dtv * A[n]);
            p[n] *= da;
            h[n] = da * h[n] + dtx * sB[j][n];
        }
    }
#pragma unroll
    for (int n = 0; n < NS; n++) {
        const size_t o = ((size_t)((b * SEG + s) * NS + n)) * DIN + d;
        g_segA[o] = p[n];
        g_segB[o] = h[n];
    }
}

__global__ __launch_bounds__(256) void scan_pass2() {
    const int gidx = blockIdx.x * 256 + threadIdx.x;
    if (gidx >= BB * DIN) return;
    const int b = gidx / DIN;
    const int d = gidx % DIN;
    float h[NS];
#pragma unroll
    for (int n = 0; n < NS; n++) h[n] = 0.f;
    for (int s = 0; s < SEG; s++) {
#pragma unroll
        for (int n = 0; n < NS; n++) {
            const size_t o = ((size_t)((b * SEG + s) * NS + n)) * DIN + d;
            g_hin[o] = h[n];
            h[n] = g_segA[o] * h[n] + g_segB[o];
        }
    }
}

__global__ __launch_bounds__(128) void scan_pass3(const float* __restrict__ A_log,
                                                  const float* __restrict__ D_skip) {
    const int b = blockIdx.z;
    const int s = blockIdx.y;
    const int d = blockIdx.x * 128 + threadIdx.x;
    const int tid = threadIdx.x;
    const int l0 = s * SEGL;

    float A[NS];
#pragma unroll
    for (int n = 0; n < NS; n++) A[n] = -__expf(A_log[d * NS + n]);
    const float dsk = D_skip[d];

    float h[NS];
#pragma unroll
    for (int n = 0; n < NS; n++)
        h[n] = g_hin[((size_t)((b * SEG + s) * NS + n)) * DIN + d];

    __shared__ float sB[SEGL][NS];
    __shared__ float sC[SEGL][NS];
    for (int i = tid; i < SEGL * NS * 2; i += 128) {
        const int ll = i >> 4;
        const int c = i & 15;
        const float v = g_dbl[((size_t)(b * LL + l0 + ll)) * DBLW + RR + c];
        if (c < NS) sB[ll][c] = v;
        else        sC[ll][c - NS] = v;
    }
    __syncthreads();

    for (int j = 0; j < SEGL; j++) {
        const size_t idx = ((size_t)(b * LL + l0 + j)) * DIN + d;
        const float dtv = g_dt[idx];
        const float xv = g_xconv[idx];
        const float dtx = dtv * xv;
        float yv = 0.f;
#pragma unroll
        for (int n = 0; n < NS; n++) {
            const float da = __expf(dtv * A[n]);
            h[n] = da * h[n] + dtx * sB[j][n];
            yv += h[n] * sC[j][n];
        }
        const float z = g_xz[((size_t)(b * LL + l0 + j)) * (2 * DIN) + DIN + d];
        const float sz = z / (1.f + __expf(-z));
        g_y[idx] = rnd_tf32((yv + dsk * xv) * sz);
    }
}

// ---------------- launch ----------------
extern "C" void kernel_launch(void* const* d_in, const int* in_sizes, int n_in,
                              void* d_out, int out_size) {
    const float* hidden = (const float*)d_in[0];
    const float* norm_w = (const float*)d_in[1];
    const float* in_proj_w = (const float*)d_in[2];
    const float* conv_w = (const float*)d_in[3];
    const float* conv_b = (const float*)d_in[4];
    const float* x_proj_w = (const float*)d_in[5];
    const float* dt_proj_w = (const float*)d_in[6];
    const float* dt_proj_b = (const float*)d_in[7];
    const float* A_log = (const float*)d_in[8];
    const float* D_skip = (const float*)d_in[9];
    const float* out_proj_w = (const float*)d_in[10];
    float* out = (float*)d_out;

    float *p_xnorm, *p_xz, *p_xconv, *p_dbl, *p_dblp, *p_dt, *p_y;
    float *p_w_in, *p_w_x, *p_w_dt, *p_w_out;
    cudaGetSymbolAddress((void**)&p_xnorm, g_xnorm);
    cudaGetSymbolAddress((void**)&p_xz, g_xz);
    cudaGetSymbolAddress((void**)&p_xconv, g_xconv);
    cudaGetSymbolAddress((void**)&p_dbl, g_dbl);
    cudaGetSymbolAddress((void**)&p_dblp, g_dblp);
    cudaGetSymbolAddress((void**)&p_dt, g_dt);
    cudaGetSymbolAddress((void**)&p_y, g_y);
    cudaGetSymbolAddress((void**)&p_w_in, g_w_in);
    cudaGetSymbolAddress((void**)&p_w_x, g_w_x);
    cudaGetSymbolAddress((void**)&p_w_dt, g_w_dt);
    cudaGetSymbolAddress((void**)&p_w_out, g_w_out);

    cudaFuncSetAttribute(gemm_tf32, cudaFuncAttributeMaxDynamicSharedMemorySize, GSMEM);

    const int M = MTOT;

    // 0. weights -> tf32
    {
        const int total4 = (NWI + NWX + NWDT + NWO) / 4;
        cvt_weights<<<(total4 + 255) / 256, 256>>>((const float4*)in_proj_w,
                                                   (const float4*)x_proj_w,
                                                   (const float4*)dt_proj_w,
                                                   (const float4*)out_proj_w);
    }

    // 1. RMSNorm
    rmsnorm_kernel<<<M, 256>>>(hidden, norm_w);

    // 2. in_proj: xz[M,2048]
    {
        dim3 grid(2 * DIN / 128, M / 128, 1);
        gemm_tf32<<<grid, 256, GSMEM>>>(p_xnorm, DD, p_w_in, DD,
                                        p_xz, 2 * DIN, 0, DD, 2 * DIN, nullptr, 0);
    }

    // 3. conv + silu
    {
        const int total = (MTOT / 8) * (DIN / 4);
        conv_silu_kernel<<<(total + 255) / 256, 256>>>(conv_w, conv_b);
    }

    // 4. x_proj split-K
    {
        dim3 grid(1, M / 128, SPLITK);
        gemm_tf32<<<grid, 256, GSMEM>>>(p_xconv, DIN, p_w_x, DIN,
                                        p_dblp, DBLW, (size_t)MTOT * DBLW,
                                        DIN / SPLITK, DBLW, nullptr, 0);
        reduce_dbl<<<(MTOT * DBLW + 255) / 256, 256>>>();
    }

    // 5. dt_proj + bias + softplus
    {
        dim3 grid(DIN / 128, M / 128, 1);
        gemm_tf32<<<grid, 256, GSMEM>>>(p_dbl, DBLW, p_w_dt, RR,
                                        p_dt, DIN, 0, RR, DIN, dt_proj_b, 1);
    }

    // 6. selective scan
    {
        dim3 grid1(DIN / 128, SEG, BB);
        scan_pass1<<<grid1, 128>>>(A_log);
        scan_pass2<<<(BB * DIN + 255) / 256, 256>>>();
        scan_pass3<<<grid1, 128>>>(A_log, D_skip);
    }

    // 7. out_proj
    {
        dim3 grid(DD / 128, M / 128, 1);
        gemm_tf32<<<grid, 256, GSMEM>>>(p_y, DIN, p_w_out, DIN,
                                        out, DD, 0, DIN, DD, nullptr, 0);
    }
}

// round 9
// speedup vs baseline: 1.1640x; 1.0165x over previous
#include <cuda_runtime.h>
#include <math.h>
#include <stdint.h>

#define BB 4
#define LL 2048
#define DD 1024
#define DIN 1024
#define NS 8
#define RR 64
#define DBLW 80
#define SEG 32
#define SEGL (LL/SEG)     // 64
#define MTOT (BB*LL)
#define SPLITK 4

// ---------------- scratch ----------------
__device__ float g_xnorm[MTOT*DD];
__device__ float g_xz[MTOT*2*DIN];
__device__ float g_xconv[MTOT*DIN];
__device__ float g_dbl[MTOT*DBLW];
__device__ float g_dblp[SPLITK*MTOT*DBLW];
__device__ float g_dt[MTOT*DIN];
__device__ float g_y[MTOT*DIN];
__device__ float g_segA[BB*SEG*NS*DIN];
__device__ float g_segB[BB*SEG*NS*DIN];
__device__ float g_hin[BB*SEG*NS*DIN];
__device__ float g_w_in[2*DIN*DD];
__device__ float g_w_x[DBLW*DIN];
__device__ float g_w_dt[DIN*RR];
__device__ float g_w_out[DD*DIN];

// ---------------- helpers ----------------
__device__ __forceinline__ float rnd_tf32(float f) {
    uint32_t u;
    asm("cvt.rna.tf32.f32 %0, %1;" : "=r"(u) : "f"(f));
    return __uint_as_float(u);
}

__device__ __forceinline__ void mma_tf32(float c[4], const uint32_t a[4], const uint32_t b[2]) {
    asm volatile(
        "mma.sync.aligned.m16n8k8.row.col.f32.tf32.tf32.f32 "
        "{%0,%1,%2,%3}, {%4,%5,%6,%7}, {%8,%9}, {%0,%1,%2,%3};"
        : "+f"(c[0]), "+f"(c[1]), "+f"(c[2]), "+f"(c[3])
        : "r"(a[0]), "r"(a[1]), "r"(a[2]), "r"(a[3]), "r"(b[0]), "r"(b[1]));
}

__device__ __forceinline__ void cp16(uint32_t dst, const void* src, bool v) {
    int sz = v ? 16 : 0;
    asm volatile("cp.async.cg.shared.global [%0], [%1], 16, %2;\n"
                 :: "r"(dst), "l"(src), "r"(sz));
}

// ---------------- weight convert (split into two launches) ----------------
#define NWI (2*DIN*DD)
#define NWX (DBLW*DIN)
#define NWDT (DIN*RR)
#define NWO (DD*DIN)

__global__ __launch_bounds__(256) void cvt_weights_big(const float4* __restrict__ iw,
                                                       const float4* __restrict__ ow) {
    int i = blockIdx.x * 256 + threadIdx.x;
    const float4* src;
    float4* dst;
    if (i < NWI/4) { src = iw + i; dst = (float4*)g_w_in + i; }
    else if ((i -= NWI/4) < NWO/4) { src = ow + i; dst = (float4*)g_w_out + i; }
    else return;
    float4 v = *src;
    v.x = rnd_tf32(v.x); v.y = rnd_tf32(v.y);
    v.z = rnd_tf32(v.z); v.w = rnd_tf32(v.w);
    *dst = v;
}

__global__ __launch_bounds__(256) void cvt_weights_small(const float4* __restrict__ xw,
                                                         const float4* __restrict__ dw) {
    int i = blockIdx.x * 256 + threadIdx.x;
    const float4* src;
    float4* dst;
    if (i < NWX/4) { src = xw + i; dst = (float4*)g_w_x + i; }
    else if ((i -= NWX/4) < NWDT/4) { src = dw + i; dst = (float4*)g_w_dt + i; }
    else return;
    float4 v = *src;
    v.x = rnd_tf32(v.x); v.y = rnd_tf32(v.y);
    v.z = rnd_tf32(v.z); v.w = rnd_tf32(v.w);
    *dst = v;
}

// ---------------- RMSNorm ----------------
__global__ __launch_bounds__(256) void rmsnorm_kernel(const float* __restrict__ x,
                                                      const float* __restrict__ w) {
    const int row = blockIdx.x;
    const float4 v = *((const float4*)(x + (size_t)row * DD) + threadIdx.x);
    float ss = v.x*v.x + v.y*v.y + v.z*v.z + v.w*v.w;
#pragma unroll
    for (int o = 16; o > 0; o >>= 1) ss += __shfl_xor_sync(0xffffffffu, ss, o);
    __shared__ float red[8];
    if ((threadIdx.x & 31) == 0) red[threadIdx.x >> 5] = ss;
    __syncthreads();
    float tot = 0.f;
#pragma unroll
    for (int i = 0; i < 8; i++) tot += red[i];
    const float sc = rsqrtf(tot * (1.f / DD) + 1e-5f);
    const float4 wv = *((const float4*)w + threadIdx.x);
    float4 o;
    o.x = rnd_tf32(v.x * sc * wv.x);
    o.y = rnd_tf32(v.y * sc * wv.y);
    o.z = rnd_tf32(v.z * sc * wv.z);
    o.w = rnd_tf32(v.w * sc * wv.w);
    *((float4*)(g_xnorm + (size_t)row * DD) + threadIdx.x) = o;
}

// ---------------- TF32 GEMM: BM=BN=128, BK=32, 256 thr, 8 warps 32x64 ----------------
#define GSTAGES 3
#define GSTRIDE 36
#define STGF (128*GSTRIDE)
#define STGB (STGF*4)
#define GSMEM (2*GSTAGES*STGB)   // 110592 bytes

__global__ __launch_bounds__(256, 2) void gemm_tf32(
    const float* __restrict__ A, int lda,
    const float* __restrict__ W, int ldw,
    float* __restrict__ C, int ldc, size_t cstride,
    int K, int E,
    const float* __restrict__ bias, int epi)
{
    extern __shared__ float smem[];
    float* sA = smem;
    float* sB = smem + GSTAGES * STGF;

    const int tid = threadIdx.x;
    const int lane = tid & 31;
    const int wid = tid >> 5;
    const int m0 = blockIdx.y * 128;
    const int e0 = blockIdx.x * 128;
    const int z = blockIdx.z;
    const int mw = (wid & 3) * 32;
    const int nw = (wid >> 2) * 64;

    const int prow = tid >> 3;        // 0..31
    const int pk = (tid & 7) * 4;     // 0..28

    const float* aP[4];
    const float* wP[4];
    bool wv[4];
    uint32_t dAo[4], dBo[4];
    const uint32_t sAu = (uint32_t)__cvta_generic_to_shared(sA);
    const uint32_t sBu = (uint32_t)__cvta_generic_to_shared(sB);
#pragma unroll
    for (int c = 0; c < 4; c++) {
        const int r = prow + 32 * c;
        aP[c] = A + (size_t)(m0 + r) * lda + (size_t)z * K + pk;
        const int er = e0 + r;
        wv[c] = er < E;
        wP[c] = W + (size_t)(wv[c] ? er : 0) * ldw + (size_t)z * K + pk;
        dAo[c] = sAu + (r * GSTRIDE + pk) * 4;
        dBo[c] = sBu + (r * GSTRIDE + pk) * 4;
    }

    float acc[2][8][4];
#pragma unroll
    for (int i = 0; i < 2; i++)
#pragma unroll
        for (int j = 0; j < 8; j++)
#pragma unroll
            for (int l = 0; l < 4; l++) acc[i][j][l] = 0.f;

    const int T = K / 32;

#pragma unroll
    for (int p = 0; p < GSTAGES - 1; p++) {
        const int ko = p * 32;
#pragma unroll
        for (int c = 0; c < 4; c++) {
            cp16(dAo[c] + p * STGB, aP[c] + ko, true);
            cp16(dBo[c] + p * STGB, wP[c] + ko, wv[c]);
        }
        asm volatile("cp.async.commit_group;\n");
    }

    const int g = lane >> 2;
    const int tg = lane & 3;

    for (int t = 0; t < T; t++) {
        asm volatile("cp.async.wait_group 1;\n");
        __syncthreads();

        // issue next-stage loads BEFORE the MMA block so they overlap compute
        {
            const int tn = t + GSTAGES - 1;
            if (tn < T) {
                const int ko = tn * 32;
                const int so = tn % GSTAGES;
#pragma unroll
                for (int c = 0; c < 4; c++) {
                    cp16(dAo[c] + so * STGB, aP[c] + ko, true);
                    cp16(dBo[c] + so * STGB, wP[c] + ko, wv[c]);
                }
            }
            asm volatile("cp.async.commit_group;\n");
        }

        const int stg = t % GSTAGES;
        const float* At = sA + stg * STGF;
        const float* Bt = sB + stg * STGF;

#pragma unroll
        for (int ks = 0; ks < 4; ks++) {
            const int kk = ks * 8;
            uint32_t af[2][4];
            uint32_t bf[8][2];
#pragma unroll
            for (int mt = 0; mt < 2; mt++) {
                const int mb = mw + mt * 16 + g;
                af[mt][0] = __float_as_uint(At[mb * GSTRIDE + kk + tg]);
                af[mt][1] = __float_as_uint(At[(mb + 8) * GSTRIDE + kk + tg]);
                af[mt][2] = __float_as_uint(At[mb * GSTRIDE + kk + 4 + tg]);
                af[mt][3] = __float_as_uint(At[(mb + 8) * GSTRIDE + kk + 4 + tg]);
            }
#pragma unroll
            for (int nt = 0; nt < 8; nt++) {
                const int nb = nw + nt * 8 + g;
                bf[nt][0] = __float_as_uint(Bt[nb * GSTRIDE + kk + tg]);
                bf[nt][1] = __float_as_uint(Bt[nb * GSTRIDE + kk + 4 + tg]);
            }
#pragma unroll
            for (int mt = 0; mt < 2; mt++)
#pragma unroll
                for (int nt = 0; nt < 8; nt++)
                    mma_tf32(acc[mt][nt], af[mt], bf[nt]);
        }
    }

    // epilogue: vectorized float2 stores (E is always even, pairs never straddle)
    float* Cz = C + (size_t)z * cstride;
#pragma unroll
    for (int mt = 0; mt < 2; mt++) {
        const int r0 = m0 + mw + mt * 16 + g;
        const int r1 = r0 + 8;
#pragma unroll
        for (int nt = 0; nt < 8; nt++) {
            const int c0 = e0 + nw + nt * 8 + tg * 2;
            if (c0 < E) {
                float va0 = acc[mt][nt][0], va1 = acc[mt][nt][1];
                float vb0 = acc[mt][nt][2], vb1 = acc[mt][nt][3];
                if (epi == 1) {
                    const float b0 = bias[c0], b1 = bias[c0 + 1];
                    va0 += b0; va0 = fmaxf(va0, 0.f) + log1pf(__expf(-fabsf(va0)));
                    va1 += b1; va1 = fmaxf(va1, 0.f) + log1pf(__expf(-fabsf(va1)));
                    vb0 += b0; vb0 = fmaxf(vb0, 0.f) + log1pf(__expf(-fabsf(vb0)));
                    vb1 += b1; vb1 = fmaxf(vb1, 0.f) + log1pf(__expf(-fabsf(vb1)));
                }
                *(float2*)(Cz + (size_t)r0 * ldc + c0) = make_float2(va0, va1);
                *(float2*)(Cz + (size_t)r1 * ldc + c0) = make_float2(vb0, vb1);
            }
        }
    }
}

// ---------------- split-K reduce for x_proj ----------------
__global__ __launch_bounds__(256) void reduce_dbl() {
    const int idx = blockIdx.x * 256 + threadIdx.x;
    if (idx >= MTOT * DBLW) return;
    float s = 0.f;
#pragma unroll
    for (int p = 0; p < SPLITK; p++) s += g_dblp[(size_t)p * MTOT * DBLW + idx];
    g_dbl[idx] = rnd_tf32(s);
}

// ---------------- conv+silu: 8l x 4d per thread ----------------
__global__ __launch_bounds__(256) void conv_silu_kernel(const float* __restrict__ conv_w,
                                                        const float* __restrict__ conv_b) {
    const int t = blockIdx.x * 256 + threadIdx.x;
    const int nd4 = DIN / 4;
    const int d0 = (t % nd4) * 4;
    const int m0 = (t / nd4) * 8;
    if (m0 >= MTOT) return;
    const int l0 = m0 % LL;
    const int b = m0 / LL;

    float4 xr[11];
#pragma unroll
    for (int j = 0; j < 11; j++) {
        const int ls = l0 - 3 + j;
        if (ls >= 0)
            xr[j] = *(const float4*)(g_xz + ((size_t)(b * LL + ls)) * (2 * DIN) + d0);
        else
            xr[j] = make_float4(0.f, 0.f, 0.f, 0.f);
    }
    float4 w0 = *(const float4*)(conv_w + (d0 + 0) * 4);
    float4 w1 = *(const float4*)(conv_w + (d0 + 1) * 4);
    float4 w2 = *(const float4*)(conv_w + (d0 + 2) * 4);
    float4 w3 = *(const float4*)(conv_w + (d0 + 3) * 4);
    const float4 bv = *(const float4*)(conv_b + d0);

#pragma unroll
    for (int i = 0; i < 8; i++) {
        float4 acc;
        acc.x = bv.x + w0.x * xr[i].x + w0.y * xr[i+1].x + w0.z * xr[i+2].x + w0.w * xr[i+3].x;
        acc.y = bv.y + w1.x * xr[i].y + w1.y * xr[i+1].y + w1.z * xr[i+2].y + w1.w * xr[i+3].y;
        acc.z = bv.z + w2.x * xr[i].z + w2.y * xr[i+1].z + w2.z * xr[i+2].z + w2.w * xr[i+3].z;
        acc.w = bv.w + w3.x * xr[i].w + w3.y * xr[i+1].w + w3.z * xr[i+2].w + w3.w * xr[i+3].w;
        float4 o;
        o.x = rnd_tf32(acc.x / (1.f + __expf(-acc.x)));
        o.y = rnd_tf32(acc.y / (1.f + __expf(-acc.y)));
        o.z = rnd_tf32(acc.z / (1.f + __expf(-acc.z)));
        o.w = rnd_tf32(acc.w / (1.f + __expf(-acc.w)));
        *(float4*)(g_xconv + ((size_t)(m0 + i)) * DIN + d0) = o;
    }
}

// ---------------- chunked selective scan (SEG=32) ----------------
__global__ __launch_bounds__(128) void scan_pass1(const float* __restrict__ A_log) {
    const int b = blockIdx.z;
    const int s = blockIdx.y;
    const int d = blockIdx.x * 128 + threadIdx.x;
    const int tid = threadIdx.x;
    const int l0 = s * SEGL;

    float A[NS];
#pragma unroll
    for (int n = 0; n < NS; n++) A[n] = -__expf(A_log[d * NS + n]);

    float p[NS], h[NS];
#pragma unroll
    for (int n = 0; n < NS; n++) { p[n] = 1.f; h[n] = 0.f; }

    __shared__ float sB[SEGL][NS];
    for (int i = tid; i < SEGL * NS; i += 128) {
        const int ll = i >> 3;
        const int n = i & 7;
        sB[ll][n] = g_dbl[((size_t)(b * LL + l0 + ll)) * DBLW + RR + n];
    }
    __syncthreads();

    for (int j = 0; j < SEGL; j++) {
        const size_t idx = ((size_t)(b * LL + l0 + j)) * DIN + d;
        const float dtv = g_dt[idx];
        const float xv = g_xconv[idx];
        const float dtx = dtv * xv;
#pragma unroll
        for (int n = 0; n < NS; n++) {
            const float da = __expf(dtv * A[n]);
            p[n] *= da;
            h[n] = da * h[n] + dtx * sB[j][n];
        }
    }
#pragma unroll
    for (int n = 0; n < NS; n++) {
        const size_t o = ((size_t)((b * SEG + s) * NS + n)) * DIN + d;
        g_segA[o] = p[n];
        g_segB[o] = h[n];
    }
}

__global__ __launch_bounds__(256) void scan_pass2() {
    const int gidx = blockIdx.x * 256 + threadIdx.x;
    if (gidx >= BB * DIN) return;
    const int b = gidx / DIN;
    const int d = gidx % DIN;
    float h[NS];
#pragma unroll
    for (int n = 0; n < NS; n++) h[n] = 0.f;
    for (int s = 0; s < SEG; s++) {
#pragma unroll
        for (int n = 0; n < NS; n++) {
            const size_t o = ((size_t)((b * SEG + s) * NS + n)) * DIN + d;
            g_hin[o] = h[n];
            h[n] = g_segA[o] * h[n] + g_segB[o];
        }
    }
}

__global__ __launch_bounds__(128) void scan_pass3(const float* __restrict__ A_log,
                                                  const float* __restrict__ D_skip) {
    const int b = blockIdx.z;
    const int s = blockIdx.y;
    const int d = blockIdx.x * 128 + threadIdx.x;
    const int tid = threadIdx.x;
    const int l0 = s * SEGL;

    float A[NS];
#pragma unroll
    for (int n = 0; n < NS; n++) A[n] = -__expf(A_log[d * NS + n]);
    const float dsk = D_skip[d];

    float h[NS];
#pragma unroll
    for (int n = 0; n < NS; n++)
        h[n] = g_hin[((size_t)((b * SEG + s) * NS + n)) * DIN + d];

    __shared__ float sB[SEGL][NS];
    __shared__ float sC[SEGL][NS];
    for (int i = tid; i < SEGL * NS * 2; i += 128) {
        const int ll = i >> 4;
        const int c = i & 15;
        const float v = g_dbl[((size_t)(b * LL + l0 + ll)) * DBLW + RR + c];
        if (c < NS) sB[ll][c] = v;
        else        sC[ll][c - NS] = v;
    }
    __syncthreads();

    for (int j = 0; j < SEGL; j++) {
        const size_t idx = ((size_t)(b * LL + l0 + j)) * DIN + d;
        const float dtv = g_dt[idx];
        const float xv = g_xconv[idx];
        const float dtx = dtv * xv;
        float yv = 0.f;
#pragma unroll
        for (int n = 0; n < NS; n++) {
            const float da = __expf(dtv * A[n]);
            h[n] = da * h[n] + dtx * sB[j][n];
            yv += h[n] * sC[j][n];
        }
        const float z = g_xz[((size_t)(b * LL + l0 + j)) * (2 * DIN) + DIN + d];
        const float sz = z / (1.f + __expf(-z));
        g_y[idx] = rnd_tf32((yv + dsk * xv) * sz);
    }
}

// ---------------- launch ----------------
extern "C" void kernel_launch(void* const* d_in, const int* in_sizes, int n_in,
                              void* d_out, int out_size) {
    const float* hidden = (const float*)d_in[0];
    const float* norm_w = (const float*)d_in[1];
    const float* in_proj_w = (const float*)d_in[2];
    const float* conv_w = (const float*)d_in[3];
    const float* conv_b = (const float*)d_in[4];
    const float* x_proj_w = (const float*)d_in[5];
    const float* dt_proj_w = (const float*)d_in[6];
    const float* dt_proj_b = (const float*)d_in[7];
    const float* A_log = (const float*)d_in[8];
    const float* D_skip = (const float*)d_in[9];
    const float* out_proj_w = (const float*)d_in[10];
    float* out = (float*)d_out;

    float *p_xnorm, *p_xz, *p_xconv, *p_dbl, *p_dblp, *p_dt, *p_y;
    float *p_w_in, *p_w_x, *p_w_dt, *p_w_out;
    cudaGetSymbolAddress((void**)&p_xnorm, g_xnorm);
    cudaGetSymbolAddress((void**)&p_xz, g_xz);
    cudaGetSymbolAddress((void**)&p_xconv, g_xconv);
    cudaGetSymbolAddress((void**)&p_dbl, g_dbl);
    cudaGetSymbolAddress((void**)&p_dblp, g_dblp);
    cudaGetSymbolAddress((void**)&p_dt, g_dt);
    cudaGetSymbolAddress((void**)&p_y, g_y);
    cudaGetSymbolAddress((void**)&p_w_in, g_w_in);
    cudaGetSymbolAddress((void**)&p_w_x, g_w_x);
    cudaGetSymbolAddress((void**)&p_w_dt, g_w_dt);
    cudaGetSymbolAddress((void**)&p_w_out, g_w_out);

    cudaFuncSetAttribute(gemm_tf32, cudaFuncAttributeMaxDynamicSharedMemorySize, GSMEM);

    const int M = MTOT;

    // 0a. big weights -> tf32   (launch 1)
    {
        const int total4 = (NWI + NWO) / 4;
        cvt_weights_big<<<(total4 + 255) / 256, 256>>>((const float4*)in_proj_w,
                                                       (const float4*)out_proj_w);
    }
    // 0b. small weights -> tf32 (launch 2)
    {
        const int total4 = (NWX + NWDT) / 4;
        cvt_weights_small<<<(total4 + 255) / 256, 256>>>((const float4*)x_proj_w,
                                                         (const float4*)dt_proj_w);
    }

    // 1. RMSNorm (launch 3)
    rmsnorm_kernel<<<M, 256>>>(hidden, norm_w);

    // 2. in_proj (launch 4 — ncu capture window)
    {
        dim3 grid(2 * DIN / 128, M / 128, 1);
        gemm_tf32<<<grid, 256, GSMEM>>>(p_xnorm, DD, p_w_in, DD,
                                        p_xz, 2 * DIN, 0, DD, 2 * DIN, nullptr, 0);
    }

    // 3. conv + silu
    {
        const int total = (MTOT / 8) * (DIN / 4);
        conv_silu_kernel<<<(total + 255) / 256, 256>>>(conv_w, conv_b);
    }

    // 4. x_proj split-K
    {
        dim3 grid(1, M / 128, SPLITK);
        gemm_tf32<<<grid, 256, GSMEM>>>(p_xconv, DIN, p_w_x, DIN,
                                        p_dblp, DBLW, (size_t)MTOT * DBLW,
                                        DIN / SPLITK, DBLW, nullptr, 0);
        reduce_dbl<<<(MTOT * DBLW + 255) / 256, 256>>>();
    }

    // 5. dt_proj + bias + softplus
    {
        dim3 grid(DIN / 128, M / 128, 1);
        gemm_tf32<<<grid, 256, GSMEM>>>(p_dbl, DBLW, p_w_dt, RR,
                                        p_dt, DIN, 0, RR, DIN, dt_proj_b, 1);
    }

    // 6. selective scan
    {
        dim3 grid1(DIN / 128, SEG, BB);
        scan_pass1<<<grid1, 128>>>(A_log);
        scan_pass2<<<(BB * DIN + 255) / 256, 256>>>();
        scan_pass3<<<grid1, 128>>>(A_log, D_skip);
    }

    // 7. out_proj
    {
        dim3 grid(DD / 128, M / 128, 1);
        gemm_tf32<<<grid, 256, GSMEM>>>(p_y, DIN, p_w_out, DIN,
                                        out, DD, 0, DIN, DD, nullptr, 0);
    }
}